// round 12
// baseline (speedup 1.0000x reference)
#include <cuda_runtime.h>
#include <cuda_bf16.h>
#include <cstdint>

// Output: 8192 x 8192 fp32, zeros except diag(triggers * mask).
//
// Last untested mechanism: bulk-copy stores (cp.async.bulk, TMA-class
// engine) instead of SM-side STG. Bypasses the L1tex store pipeline
// (co-limiter at ~68% in every STG profile): each CTA zeroes one 32KB
// SMEM tile and streams it to 4 contiguous rows (128KB contiguous GMEM)
// with 4 bulk stores, then patches its 4 diagonal elements after
// wait_group 0 (async writes complete+visible before the generic STG).

static constexpr int N = 8192;                 // row = 8192 floats = 32 KB
static constexpr int ROWS_PER_CTA = 4;         // 128 KB contiguous per CTA
static constexpr int CTAS = N / ROWS_PER_CTA;  // 2048
static constexpr int TPB = 256;
static constexpr unsigned ROW_BYTES = N * 4;   // 32768

__global__ void __launch_bounds__(TPB)
fill_diag_kernel(const float* __restrict__ triggers,
                 const int* __restrict__ mask,
                 float* __restrict__ out) {
    __shared__ __align__(128) float tile[N];   // 32 KB zero tile

    const int tid = threadIdx.x;
    const int b   = blockIdx.x;
    const int r0  = b * ROWS_PER_CTA;

    // Early diag-input load (tiny; hides under the tile zeroing + bulk ops)
    float dval = 0.0f;
    if (tid < ROWS_PER_CTA) {
        const int r = r0 + tid;
        dval = triggers[r] * (float)mask[r];
    }

    // Zero the SMEM tile (128B stores, no conflicts)
#pragma unroll 8
    for (int i = tid; i < N / 4; i += TPB) {
        ((float4*)tile)[i] = make_float4(0.f, 0.f, 0.f, 0.f);
    }
    __syncthreads();

    // Make generic-proxy SMEM writes visible to the async (bulk) proxy.
    asm volatile("fence.proxy.async.shared::cta;" ::: "memory");

    if (tid == 0) {
        uint32_t smem_addr;
        asm("{ .reg .u64 t; cvta.to.shared.u64 t, %1; cvt.u32.u64 %0, t; }"
            : "=r"(smem_addr) : "l"(tile));
        float* gdst = out + (size_t)r0 * N;
#pragma unroll
        for (int j = 0; j < ROWS_PER_CTA; j++) {
            asm volatile(
                "cp.async.bulk.global.shared::cta.bulk_group [%0], [%1], %2;"
                :: "l"(gdst + (size_t)j * N), "r"(smem_addr), "r"(ROW_BYTES)
                : "memory");
        }
        asm volatile("cp.async.bulk.commit_group;" ::: "memory");
        asm volatile("cp.async.bulk.wait_group 0;" ::: "memory");
    }
    __syncthreads();   // bulk writes complete + visible to all threads

    // Diagonal fix-up: rows r0..r0+3, element (r, r).
    if (tid < ROWS_PER_CTA) {
        const size_t r = (size_t)(r0 + tid);
        out[r * (N + 1)] = dval;
    }
}

extern "C" void kernel_launch(void* const* d_in, const int* in_sizes, int n_in,
                              void* d_out, int out_size) {
    const float* triggers = (const float*)d_in[0];
    const int*   mask     = (const int*)d_in[1];
    float*       out      = (float*)d_out;

    fill_diag_kernel<<<CTAS, TPB>>>(triggers, mask, out);
}